// round 6
// baseline (speedup 1.0000x reference)
#include <cuda_runtime.h>
#include <cstdint>
#include <cstddef>

#define DM 19
#define HID 512
#define NH 8
#define DH 64
#define BB 16
#define LL 1024
#define NTOK (BB*LL)

#define OUT_ELEMS   (NTOK*DM)
#define ATTN_ELEMS  ((size_t)BB*NH*LL*LL)

// ---- scratch ----
__device__ float g_q [(size_t)BB*NH*LL*DH];   // [bh][l][d]
__device__ float g_k [(size_t)BB*NH*LL*DH];   // [bh][l][d]
__device__ float g_kT[(size_t)BB*NH*DH*LL];   // [bh][d][l]
__device__ float g_v [(size_t)BB*NH*LL*DH];   // [bh][l][d]
__device__ float g_ctx[(size_t)NTOK*HID];     // [n][512]

// =====================================================================
// Kernel 1: QKV projections
// =====================================================================
__global__ void proj_kernel(const float* __restrict__ Xq, const float* __restrict__ Xk,
                            const float* __restrict__ Xv,
                            const float* __restrict__ Wq, const float* __restrict__ Wk,
                            const float* __restrict__ Wv,
                            const float* __restrict__ bq, const float* __restrict__ bk,
                            const float* __restrict__ bv) {
    __shared__ float sW[DM*HID];
    __shared__ float sX[32*20];
    const int which = blockIdx.y;
    const float* X    = (which == 0) ? Xq : (which == 1) ? Xk : Xv;
    const float* W    = (which == 0) ? Wq : (which == 1) ? Wk : Wv;
    const float* bias = (which == 0) ? bq : (which == 1) ? bk : bv;
    float* dst        = (which == 0) ? g_q : (which == 1) ? g_k : g_v;

    const int t = threadIdx.x;
    for (int i = t; i < DM*HID; i += 256) sW[i] = W[i];
    const int base = blockIdx.x * 32;
    for (int i = t; i < 32*DM; i += 256) {
        int r = i / DM, m = i - r*DM;
        sX[r*20 + m] = X[(size_t)(base + r)*DM + m];
    }
    __syncthreads();

    const int bidx = base >> 10;
    const int lbase = base & 1023;
    #pragma unroll
    for (int cc = 0; cc < 2; cc++) {
        const int c = t + cc*256;
        const int h = c >> 6, d = c & 63;
        float* dp = dst + ((size_t)(bidx*NH + h)*LL + lbase)*DH + d;
        const float bval = bias[c];
        for (int r = 0; r < 32; r++) {
            float acc = bval;
            #pragma unroll
            for (int m = 0; m < DM; m++) acc += sX[r*20 + m] * sW[m*HID + c];
            dp[(size_t)r*DH] = acc;
        }
    }
}

// =====================================================================
// Kernel 1b: K transpose  g_k[bh][l][d] -> g_kT[bh][d][l]
// grid (8, 128), block 256
// =====================================================================
__global__ void transpose_k_kernel() {
    __shared__ float ts[128*65];
    const int t = threadIdx.x;
    const int bh = blockIdx.y;
    const int lbase = blockIdx.x * 128;
    const float* src = g_k + ((size_t)bh*LL + lbase)*DH;
    #pragma unroll
    for (int j = 0; j < 8; j++) {
        int idx = t + j*256;
        int r = idx >> 4, d4 = (idx & 15)*4;
        float4 a = *(const float4*)(src + (size_t)r*DH + d4);
        ts[r*65 + d4 + 0] = a.x; ts[r*65 + d4 + 1] = a.y;
        ts[r*65 + d4 + 2] = a.z; ts[r*65 + d4 + 3] = a.w;
    }
    __syncthreads();
    float* dstb = g_kT + (size_t)bh*DH*LL + lbase;
    #pragma unroll
    for (int j = 0; j < 8; j++) {
        int idx = t + j*256;
        int d = idx >> 5, c = (idx & 31)*4;
        float4 o;
        o.x = ts[(c+0)*65 + d]; o.y = ts[(c+1)*65 + d];
        o.z = ts[(c+2)*65 + d]; o.w = ts[(c+3)*65 + d];
        *(float4*)(dstb + (size_t)d*LL + c) = o;
    }
}

// =====================================================================
// Kernel 2: fused attention, one (b,h) x 32-query strip.
// S[32][1024] in smem. Scores use transposed K tiles (conflict-free LDS),
// 4q x 4k register tile; PV uses 4q x 4d tile with half-split kk range.
// grid (32, 128), block 256
// =====================================================================
#define MQ 32
#define KTILE 128
#define NKT (LL/KTILE)      // 8
#define KP 128              // kT tile pitch (floats)
#define VP 68               // v tile pitch (floats)

__global__ __launch_bounds__(256, 1)
void attn_kernel(const int* __restrict__ mask, float* __restrict__ attn_out) {
    extern __shared__ float sm[];
    float* S    = sm;                       // 32*1024          = 32768 f
    float* kv   = S  + MQ*LL;               // max(64*128,128*68)= 8704 f
    float* qT   = kv + KTILE*VP;            // 64*32            = 2048 f
    float* cbuf = qT + DH*32;               // 32*68            = 2176 f
    __shared__ float sinv[MQ];

    const int t = threadIdx.x;
    const int warp = t >> 5, lane = t & 31;
    const int bh = blockIdx.y, b = bh >> 3, h = bh & 7;
    const int qbase = blockIdx.x * MQ;

    const float* gq  = g_q  + ((size_t)bh*LL + qbase)*DH;
    const float* gkT = g_kT + (size_t)bh*DH*LL;
    const float* gv  = g_v  + (size_t)bh*LL*DH;

    // build qT[d][q]  (pitch 32)
    {
        int r = t >> 3, d0 = (t & 7)*8;
        float4 a = *(const float4*)(gq + (size_t)r*DH + d0);
        float4 b4 = *(const float4*)(gq + (size_t)r*DH + d0 + 4);
        qT[(d0+0)*32 + r] = a.x;  qT[(d0+1)*32 + r] = a.y;
        qT[(d0+2)*32 + r] = a.z;  qT[(d0+3)*32 + r] = a.w;
        qT[(d0+4)*32 + r] = b4.x; qT[(d0+5)*32 + r] = b4.y;
        qT[(d0+6)*32 + r] = b4.z; qT[(d0+7)*32 + r] = b4.w;
    }

    const int q0 = 4*warp;          // warp owns 4 q rows
    const int k0 = 4*lane;          // lane owns 4 k cols within tile
    const float INVSCALE = 0.13258252147247766f;   // sqrt(9/512)

    // ---------------- scores ----------------
    float4 pf[8];
    #pragma unroll
    for (int j = 0; j < 8; j++) {
        int idx = t + j*256; int d = idx >> 5, c = (idx & 31)*4;
        pf[j] = *(const float4*)(gkT + (size_t)d*LL + c);
    }
    for (int kt = 0; kt < NKT; kt++) {
        __syncthreads();                       // buffer free (also covers qT, iter 0)
        #pragma unroll
        for (int j = 0; j < 8; j++) {
            int idx = t + j*256; int d = idx >> 5, c = (idx & 31)*4;
            *(float4*)(kv + d*KP + c) = pf[j];
        }
        __syncthreads();
        if (kt + 1 < NKT) {
            const int kb2 = (kt+1)*KTILE;
            #pragma unroll
            for (int j = 0; j < 8; j++) {
                int idx = t + j*256; int d = idx >> 5, c = (idx & 31)*4;
                pf[j] = *(const float4*)(gkT + (size_t)d*LL + kb2 + c);
            }
        }
        const int kb = kt*KTILE;
        int4 m[4];
        #pragma unroll
        for (int i = 0; i < 4; i++)
            m[i] = *(const int4*)(mask + ((size_t)b*LL + qbase + q0 + i)*LL + kb + k0);

        float acc[4][4] = {};
        #pragma unroll 8
        for (int d = 0; d < DH; d++) {
            float4 qv = *(const float4*)(qT + d*32 + q0);   // broadcast
            float4 kk = *(const float4*)(kv + d*KP + k0);   // conflict-free
            acc[0][0] += qv.x*kk.x; acc[0][1] += qv.x*kk.y; acc[0][2] += qv.x*kk.z; acc[0][3] += qv.x*kk.w;
            acc[1][0] += qv.y*kk.x; acc[1][1] += qv.y*kk.y; acc[1][2] += qv.y*kk.z; acc[1][3] += qv.y*kk.w;
            acc[2][0] += qv.z*kk.x; acc[2][1] += qv.z*kk.y; acc[2][2] += qv.z*kk.z; acc[2][3] += qv.z*kk.w;
            acc[3][0] += qv.w*kk.x; acc[3][1] += qv.w*kk.y; acc[3][2] += qv.w*kk.z; acc[3][3] += qv.w*kk.w;
        }
        #pragma unroll
        for (int i = 0; i < 4; i++) {
            float4 s;
            s.x = m[i].x ? -1e9f : acc[i][0]*INVSCALE;
            s.y = m[i].y ? -1e9f : acc[i][1]*INVSCALE;
            s.z = m[i].z ? -1e9f : acc[i][2]*INVSCALE;
            s.w = m[i].w ? -1e9f : acc[i][3]*INVSCALE;
            *(float4*)(S + (q0+i)*LL + kb + k0) = s;
        }
    }
    __syncthreads();

    // ---------------- softmax: raw exp kept in S, normalized attn written out ----------------
    for (int rr = 0; rr < 4; rr++) {
        const int row = warp*4 + rr;
        float* Sr = S + row*LL;
        float mx = -1e30f;
        for (int i = lane; i < LL; i += 32) mx = fmaxf(mx, Sr[i]);
        #pragma unroll
        for (int o = 16; o; o >>= 1) mx = fmaxf(mx, __shfl_xor_sync(~0u, mx, o));
        float sum = 0.f;
        for (int i = lane; i < LL; i += 32) {
            float e = __expf(Sr[i] - mx);
            Sr[i] = e;
            sum += e;
        }
        #pragma unroll
        for (int o = 16; o; o >>= 1) sum += __shfl_xor_sync(~0u, sum, o);
        const float inv = 1.0f / sum;
        if (lane == 0) sinv[row] = inv;
        __syncwarp();
        float* arow = attn_out + ((size_t)bh*LL + qbase + row)*LL;
        for (int i = lane*4; i < LL; i += 128) {
            float4 e4 = *(float4*)(Sr + i);
            float4 p; p.x = e4.x*inv; p.y = e4.y*inv; p.z = e4.z*inv; p.w = e4.w*inv;
            *(float4*)(arow + i) = p;
        }
    }

    // ---------------- PV: ctx[32][64] = (raw-exp S) @ V, scale by sinv at end ----------------
    // thread: warp -> 4 q rows; lane: half = lane>>4 (kk half), dg = lane&15 -> 4 d cols
    const int half = lane >> 4;
    const int pd = 4*(lane & 15);
    float c[4][4] = {};

    #pragma unroll
    for (int j = 0; j < 8; j++) {
        int idx = t + j*256; int r = idx >> 4, d4 = (idx & 15)*4;
        pf[j] = *(const float4*)(gv + (size_t)r*DH + d4);
    }
    for (int kt = 0; kt < NKT; kt++) {
        __syncthreads();
        #pragma unroll
        for (int j = 0; j < 8; j++) {
            int idx = t + j*256; int r = idx >> 4, d4 = (idx & 15)*4;
            *(float4*)(kv + r*VP + d4) = pf[j];
        }
        __syncthreads();
        if (kt + 1 < NKT) {
            const int kb2 = (kt+1)*KTILE;
            #pragma unroll
            for (int j = 0; j < 8; j++) {
                int idx = t + j*256; int r = idx >> 4, d4 = (idx & 15)*4;
                pf[j] = *(const float4*)(gv + (size_t)(kb2 + r)*DH + d4);
            }
        }
        const float* Sr0 = S + (q0+0)*LL + kt*KTILE + half*64;
        const float* Sr1 = S + (q0+1)*LL + kt*KTILE + half*64;
        const float* Sr2 = S + (q0+2)*LL + kt*KTILE + half*64;
        const float* Sr3 = S + (q0+3)*LL + kt*KTILE + half*64;
        const float* vb = kv + half*64*VP + pd;
        #pragma unroll 4
        for (int kk = 0; kk < 64; kk += 2) {
            float4 v0 = *(const float4*)(vb + kk*VP);
            float4 v1 = *(const float4*)(vb + (kk+1)*VP);
            float2 s0 = *(const float2*)(Sr0 + kk);
            float2 s1 = *(const float2*)(Sr1 + kk);
            float2 s2 = *(const float2*)(Sr2 + kk);
            float2 s3 = *(const float2*)(Sr3 + kk);
            c[0][0] += s0.x*v0.x + s0.y*v1.x; c[0][1] += s0.x*v0.y + s0.y*v1.y;
            c[0][2] += s0.x*v0.z + s0.y*v1.z; c[0][3] += s0.x*v0.w + s0.y*v1.w;
            c[1][0] += s1.x*v0.x + s1.y*v1.x; c[1][1] += s1.x*v0.y + s1.y*v1.y;
            c[1][2] += s1.x*v0.z + s1.y*v1.z; c[1][3] += s1.x*v0.w + s1.y*v1.w;
            c[2][0] += s2.x*v0.x + s2.y*v1.x; c[2][1] += s2.x*v0.y + s2.y*v1.y;
            c[2][2] += s2.x*v0.z + s2.y*v1.z; c[2][3] += s2.x*v0.w + s2.y*v1.w;
            c[3][0] += s3.x*v0.x + s3.y*v1.x; c[3][1] += s3.x*v0.y + s3.y*v1.y;
            c[3][2] += s3.x*v0.z + s3.y*v1.z; c[3][3] += s3.x*v0.w + s3.y*v1.w;
        }
    }
    // reduce the two kk-halves through cbuf
    __syncthreads();
    if (half == 0) {
        #pragma unroll
        for (int i = 0; i < 4; i++)
            *(float4*)(cbuf + (q0+i)*VP + pd) = make_float4(c[i][0], c[i][1], c[i][2], c[i][3]);
    }
    __syncthreads();
    if (half == 1) {
        #pragma unroll
        for (int i = 0; i < 4; i++) {
            float4 o = *(float4*)(cbuf + (q0+i)*VP + pd);
            o.x += c[i][0]; o.y += c[i][1]; o.z += c[i][2]; o.w += c[i][3];
            *(float4*)(cbuf + (q0+i)*VP + pd) = o;
        }
    }
    __syncthreads();
    // final write with 1/sum scale
    {
        const int row = t >> 3, c8 = (t & 7)*8;
        const float iv = sinv[row];
        float4 a = *(float4*)(cbuf + row*VP + c8);
        float4 b4 = *(float4*)(cbuf + row*VP + c8 + 4);
        a.x *= iv; a.y *= iv; a.z *= iv; a.w *= iv;
        b4.x *= iv; b4.y *= iv; b4.z *= iv; b4.w *= iv;
        float* dp = g_ctx + ((size_t)b*LL + qbase + row)*HID + h*DH + c8;
        *(float4*)(dp)     = a;
        *(float4*)(dp + 4) = b4;
    }
}

// =====================================================================
// Kernel 3: out = LN(ctx @ Wo + bo + residual)
// =====================================================================
__global__ void outproj_kernel(const float* __restrict__ Qin, const float* __restrict__ Wo,
                               const float* __restrict__ bo, const float* __restrict__ lng,
                               const float* __restrict__ lnb, float* __restrict__ out) {
    __shared__ float sWo[HID*DM];
    __shared__ float scx[4*HID];
    __shared__ float sx[4*20];
    const int t = threadIdx.x, warp = t >> 5, lane = t & 31;
    for (int i = t; i < HID*DM; i += 128) sWo[i] = Wo[i];
    const int n = blockIdx.x*4 + warp;
    #pragma unroll
    for (int k = 0; k < 4; k++)
        *(float4*)(scx + warp*HID + lane*4 + 128*k) =
            *(const float4*)(g_ctx + (size_t)n*HID + lane*4 + 128*k);
    __syncthreads();

    float x = 0.f;
    if (lane < DM) {
        float a0 = 0.f, a1 = 0.f, a2 = 0.f, a3 = 0.f;
        const float* cs = scx + warp*HID;
        for (int i = 0; i < HID; i += 4) {
            a0 += cs[i+0]*sWo[(i+0)*DM + lane];
            a1 += cs[i+1]*sWo[(i+1)*DM + lane];
            a2 += cs[i+2]*sWo[(i+2)*DM + lane];
            a3 += cs[i+3]*sWo[(i+3)*DM + lane];
        }
        x = (a0+a1) + (a2+a3) + bo[lane] + Qin[(size_t)n*DM + lane];
        sx[warp*20 + lane] = x;
    }
    __syncwarp();
    if (lane < DM) {
        float mu = 0.f;
        #pragma unroll
        for (int j = 0; j < DM; j++) mu += sx[warp*20 + j];
        mu *= (1.0f/19.0f);
        float var = 0.f;
        #pragma unroll
        for (int j = 0; j < DM; j++) { float d = sx[warp*20 + j] - mu; var += d*d; }
        var *= (1.0f/19.0f);
        out[(size_t)n*DM + lane] = (x - mu)*rsqrtf(var + 1e-5f)*lng[lane] + lnb[lane];
    }
}

// =====================================================================
// Kernel 4: residual = Q
// =====================================================================
__global__ void copy_res_kernel(const float* __restrict__ Qin, float* __restrict__ dst) {
    const size_t i = ((size_t)blockIdx.x*256 + threadIdx.x)*4;
    *(float4*)(dst + i) = *(const float4*)(Qin + i);
}

// =====================================================================
extern "C" void kernel_launch(void* const* d_in, const int* in_sizes, int n_in,
                              void* d_out, int out_size) {
    const float* Q   = (const float*)d_in[0];
    const float* K   = (const float*)d_in[1];
    const float* V   = (const float*)d_in[2];
    const int*  mask = (const int*)d_in[3];
    const float* Wq  = (const float*)d_in[4];
    const float* bq  = (const float*)d_in[5];
    const float* Wk  = (const float*)d_in[6];
    const float* bk  = (const float*)d_in[7];
    const float* Wv  = (const float*)d_in[8];
    const float* bv  = (const float*)d_in[9];
    const float* Wo  = (const float*)d_in[10];
    const float* bo  = (const float*)d_in[11];
    const float* lng = (const float*)d_in[12];
    const float* lnb = (const float*)d_in[13];

    float* out  = (float*)d_out;
    float* attn = out + OUT_ELEMS;
    float* res  = attn + ATTN_ELEMS;

    const int ATT_SMEM = (MQ*LL + KTILE*VP + DH*32 + 32*VP) * (int)sizeof(float); // 182784
    cudaFuncSetAttribute(attn_kernel, cudaFuncAttributeMaxDynamicSharedMemorySize, ATT_SMEM);

    proj_kernel<<<dim3(NTOK/32, 3), 256>>>(Q, K, V, Wq, Wk, Wv, bq, bk, bv);
    transpose_k_kernel<<<dim3(LL/128, BB*NH), 256>>>();
    attn_kernel<<<dim3(LL/MQ, BB*NH), 256, ATT_SMEM>>>(mask, attn);
    outproj_kernel<<<NTOK/4, 128>>>(Q, Wo, bo, lng, lnb, out);
    copy_res_kernel<<<OUT_ELEMS/4/256, 256>>>(Q, res);
}

// round 7
// speedup vs baseline: 1.1010x; 1.1010x over previous
#include <cuda_runtime.h>
#include <cstdint>
#include <cstddef>

#define DM 19
#define HID 512
#define NH 8
#define DH 64
#define BB 16
#define LL 1024
#define NTOK (BB*LL)

#define OUT_ELEMS   (NTOK*DM)
#define ATTN_ELEMS  ((size_t)BB*NH*LL*LL)

// ---- scratch ----
__device__ float g_q [(size_t)BB*NH*LL*DH];   // [bh][l][d]
__device__ float g_k [(size_t)BB*NH*LL*DH];   // [bh][l][d]
__device__ float g_kT[(size_t)BB*NH*DH*LL];   // [bh][d][l]
__device__ float g_v [(size_t)BB*NH*LL*DH];   // [bh][l][d]
__device__ float g_ctx[(size_t)NTOK*HID];     // [n][512]

// ---- packed fp32x2 helpers (SASS FFMA2 path; PTX-only) ----
__device__ __forceinline__ void ffma2(unsigned long long& c, unsigned long long a,
                                      unsigned long long b) {
    asm("fma.rn.f32x2 %0, %1, %2, %0;" : "+l"(c) : "l"(a), "l"(b));
}
__device__ __forceinline__ unsigned long long pk2(float x, float y) {
    unsigned long long u; asm("mov.b64 %0, {%1, %2};" : "=l"(u) : "f"(x), "f"(y)); return u;
}
__device__ __forceinline__ unsigned long long rep2(float x) {
    unsigned long long u; asm("mov.b64 %0, {%1, %1};" : "=l"(u) : "f"(x)); return u;
}
__device__ __forceinline__ float2 upk(unsigned long long u) {
    float2 r; asm("mov.b64 {%0, %1}, %2;" : "=f"(r.x), "=f"(r.y) : "l"(u)); return r;
}

// =====================================================================
// Kernel 1: QKV projections
// =====================================================================
__global__ void proj_kernel(const float* __restrict__ Xq, const float* __restrict__ Xk,
                            const float* __restrict__ Xv,
                            const float* __restrict__ Wq, const float* __restrict__ Wk,
                            const float* __restrict__ Wv,
                            const float* __restrict__ bq, const float* __restrict__ bk,
                            const float* __restrict__ bv) {
    __shared__ float sW[DM*HID];
    __shared__ float sX[32*20];
    const int which = blockIdx.y;
    const float* X    = (which == 0) ? Xq : (which == 1) ? Xk : Xv;
    const float* W    = (which == 0) ? Wq : (which == 1) ? Wk : Wv;
    const float* bias = (which == 0) ? bq : (which == 1) ? bk : bv;
    float* dst        = (which == 0) ? g_q : (which == 1) ? g_k : g_v;

    const int t = threadIdx.x;
    for (int i = t; i < DM*HID; i += 256) sW[i] = W[i];
    const int base = blockIdx.x * 32;
    for (int i = t; i < 32*DM; i += 256) {
        int r = i / DM, m = i - r*DM;
        sX[r*20 + m] = X[(size_t)(base + r)*DM + m];
    }
    __syncthreads();

    const int bidx = base >> 10;
    const int lbase = base & 1023;
    #pragma unroll
    for (int cc = 0; cc < 2; cc++) {
        const int c = t + cc*256;
        const int h = c >> 6, d = c & 63;
        float* dp = dst + ((size_t)(bidx*NH + h)*LL + lbase)*DH + d;
        const float bval = bias[c];
        for (int r = 0; r < 32; r++) {
            float acc = bval;
            #pragma unroll
            for (int m = 0; m < DM; m++) acc += sX[r*20 + m] * sW[m*HID + c];
            dp[(size_t)r*DH] = acc;
        }
    }
}

// =====================================================================
// Kernel 1b: K transpose  g_k[bh][l][d] -> g_kT[bh][d][l]
// =====================================================================
__global__ void transpose_k_kernel() {
    __shared__ float ts[128*65];
    const int t = threadIdx.x;
    const int bh = blockIdx.y;
    const int lbase = blockIdx.x * 128;
    const float* src = g_k + ((size_t)bh*LL + lbase)*DH;
    #pragma unroll
    for (int j = 0; j < 8; j++) {
        int idx = t + j*256;
        int r = idx >> 4, d4 = (idx & 15)*4;
        float4 a = *(const float4*)(src + (size_t)r*DH + d4);
        ts[r*65 + d4 + 0] = a.x; ts[r*65 + d4 + 1] = a.y;
        ts[r*65 + d4 + 2] = a.z; ts[r*65 + d4 + 3] = a.w;
    }
    __syncthreads();
    float* dstb = g_kT + (size_t)bh*DH*LL + lbase;
    #pragma unroll
    for (int j = 0; j < 8; j++) {
        int idx = t + j*256;
        int d = idx >> 5, c = (idx & 31)*4;
        float4 o;
        o.x = ts[(c+0)*65 + d]; o.y = ts[(c+1)*65 + d];
        o.z = ts[(c+2)*65 + d]; o.w = ts[(c+3)*65 + d];
        *(float4*)(dstb + (size_t)d*LL + c) = o;
    }
}

// =====================================================================
// Kernel 2: fused attention (packed f32x2 math)
// grid (32, 128), block 256
// =====================================================================
#define MQ 32
#define KTILE 128
#define NKT (LL/KTILE)
#define KP 128
#define VP 68

__global__ __launch_bounds__(256, 1)
void attn_kernel(const int* __restrict__ mask, float* __restrict__ attn_out) {
    extern __shared__ float sm[];
    float* S    = sm;                       // 32*1024
    float* kv   = S  + MQ*LL;               // 128*68 (max)
    float* qT   = kv + KTILE*VP;            // 64*32
    float* cbuf = qT + DH*32;               // 32*68
    __shared__ float sinv[MQ];

    const int t = threadIdx.x;
    const int warp = t >> 5, lane = t & 31;
    const int bh = blockIdx.y, b = bh >> 3, h = bh & 7;
    const int qbase = blockIdx.x * MQ;

    const float* gq  = g_q  + ((size_t)bh*LL + qbase)*DH;
    const float* gkT = g_kT + (size_t)bh*DH*LL;
    const float* gv  = g_v  + (size_t)bh*LL*DH;

    // build qT[d][q]
    {
        int r = t >> 3, d0 = (t & 7)*8;
        float4 a = *(const float4*)(gq + (size_t)r*DH + d0);
        float4 b4 = *(const float4*)(gq + (size_t)r*DH + d0 + 4);
        qT[(d0+0)*32 + r] = a.x;  qT[(d0+1)*32 + r] = a.y;
        qT[(d0+2)*32 + r] = a.z;  qT[(d0+3)*32 + r] = a.w;
        qT[(d0+4)*32 + r] = b4.x; qT[(d0+5)*32 + r] = b4.y;
        qT[(d0+6)*32 + r] = b4.z; qT[(d0+7)*32 + r] = b4.w;
    }

    const int q0 = 4*warp;
    const int k0 = 4*lane;
    const float INVSCALE = 0.13258252147247766f;   // sqrt(9/512)

    // ---------------- scores ----------------
    float4 pf[8];
    #pragma unroll
    for (int j = 0; j < 8; j++) {
        int idx = t + j*256; int d = idx >> 5, c = (idx & 31)*4;
        pf[j] = *(const float4*)(gkT + (size_t)d*LL + c);
    }
    for (int kt = 0; kt < NKT; kt++) {
        __syncthreads();
        #pragma unroll
        for (int j = 0; j < 8; j++) {
            int idx = t + j*256; int d = idx >> 5, c = (idx & 31)*4;
            *(float4*)(kv + d*KP + c) = pf[j];
        }
        __syncthreads();
        if (kt + 1 < NKT) {
            const int kb2 = (kt+1)*KTILE;
            #pragma unroll
            for (int j = 0; j < 8; j++) {
                int idx = t + j*256; int d = idx >> 5, c = (idx & 31)*4;
                pf[j] = *(const float4*)(gkT + (size_t)d*LL + kb2 + c);
            }
        }
        const int kb = kt*KTILE;
        int4 m[4];
        #pragma unroll
        for (int i = 0; i < 4; i++)
            m[i] = *(const int4*)(mask + ((size_t)b*LL + qbase + q0 + i)*LL + kb + k0);

        // packed accumulators: aA[i] = {S[q0+i][k0], S[q0+i][k0+1]}, aB = k2,k3
        unsigned long long aA[4] = {0ull,0ull,0ull,0ull};
        unsigned long long aB[4] = {0ull,0ull,0ull,0ull};
        #pragma unroll 8
        for (int d = 0; d < DH; d++) {
            float4 qv = *(const float4*)(qT + d*32 + q0);   // broadcast
            float4 kk = *(const float4*)(kv + d*KP + k0);   // conflict-free
            unsigned long long kA = pk2(kk.x, kk.y);
            unsigned long long kB = pk2(kk.z, kk.w);
            unsigned long long r0 = rep2(qv.x), r1 = rep2(qv.y);
            unsigned long long r2 = rep2(qv.z), r3 = rep2(qv.w);
            ffma2(aA[0], r0, kA); ffma2(aB[0], r0, kB);
            ffma2(aA[1], r1, kA); ffma2(aB[1], r1, kB);
            ffma2(aA[2], r2, kA); ffma2(aB[2], r2, kB);
            ffma2(aA[3], r3, kA); ffma2(aB[3], r3, kB);
        }
        #pragma unroll
        for (int i = 0; i < 4; i++) {
            float2 lo = upk(aA[i]), hi = upk(aB[i]);
            float4 s;
            s.x = m[i].x ? -1e9f : lo.x*INVSCALE;
            s.y = m[i].y ? -1e9f : lo.y*INVSCALE;
            s.z = m[i].z ? -1e9f : hi.x*INVSCALE;
            s.w = m[i].w ? -1e9f : hi.y*INVSCALE;
            *(float4*)(S + (q0+i)*LL + kb + k0) = s;
        }
    }
    __syncthreads();

    // ---------------- softmax ----------------
    for (int rr = 0; rr < 4; rr++) {
        const int row = warp*4 + rr;
        float* Sr = S + row*LL;
        float mx = -1e30f;
        for (int i = lane; i < LL; i += 32) mx = fmaxf(mx, Sr[i]);
        #pragma unroll
        for (int o = 16; o; o >>= 1) mx = fmaxf(mx, __shfl_xor_sync(~0u, mx, o));
        float sum = 0.f;
        for (int i = lane; i < LL; i += 32) {
            float e = __expf(Sr[i] - mx);
            Sr[i] = e;
            sum += e;
        }
        #pragma unroll
        for (int o = 16; o; o >>= 1) sum += __shfl_xor_sync(~0u, sum, o);
        const float inv = 1.0f / sum;
        if (lane == 0) sinv[row] = inv;
        __syncwarp();
        float* arow = attn_out + ((size_t)bh*LL + qbase + row)*LL;
        for (int i = lane*4; i < LL; i += 128) {
            float4 e4 = *(float4*)(Sr + i);
            float4 p; p.x = e4.x*inv; p.y = e4.y*inv; p.z = e4.z*inv; p.w = e4.w*inv;
            *(float4*)(arow + i) = p;
        }
    }

    // ---------------- PV (packed over d-pairs) ----------------
    const int half = lane >> 4;
    const int pd = 4*(lane & 15);
    // c[q][0] = {ctx[q][pd], ctx[q][pd+1]}, c[q][1] = {pd+2, pd+3}
    unsigned long long c[4][2] = {};

    #pragma unroll
    for (int j = 0; j < 8; j++) {
        int idx = t + j*256; int r = idx >> 4, d4 = (idx & 15)*4;
        pf[j] = *(const float4*)(gv + (size_t)r*DH + d4);
    }
    for (int kt = 0; kt < NKT; kt++) {
        __syncthreads();
        #pragma unroll
        for (int j = 0; j < 8; j++) {
            int idx = t + j*256; int r = idx >> 4, d4 = (idx & 15)*4;
            *(float4*)(kv + r*VP + d4) = pf[j];
        }
        __syncthreads();
        if (kt + 1 < NKT) {
            const int kb2 = (kt+1)*KTILE;
            #pragma unroll
            for (int j = 0; j < 8; j++) {
                int idx = t + j*256; int r = idx >> 4, d4 = (idx & 15)*4;
                pf[j] = *(const float4*)(gv + (size_t)(kb2 + r)*DH + d4);
            }
        }
        const float* Sr0 = S + (q0+0)*LL + kt*KTILE + half*64;
        const float* Sr1 = S + (q0+1)*LL + kt*KTILE + half*64;
        const float* Sr2 = S + (q0+2)*LL + kt*KTILE + half*64;
        const float* Sr3 = S + (q0+3)*LL + kt*KTILE + half*64;
        const float* vb = kv + half*64*VP + pd;
        #pragma unroll 4
        for (int kk = 0; kk < 64; kk += 2) {
            float4 v0 = *(const float4*)(vb + kk*VP);
            float4 v1 = *(const float4*)(vb + (kk+1)*VP);
            unsigned long long v0a = pk2(v0.x, v0.y), v0b = pk2(v0.z, v0.w);
            unsigned long long v1a = pk2(v1.x, v1.y), v1b = pk2(v1.z, v1.w);
            float2 s0 = *(const float2*)(Sr0 + kk);
            float2 s1 = *(const float2*)(Sr1 + kk);
            float2 s2 = *(const float2*)(Sr2 + kk);
            float2 s3 = *(const float2*)(Sr3 + kk);
            unsigned long long r;
            r = rep2(s0.x); ffma2(c[0][0], r, v0a); ffma2(c[0][1], r, v0b);
            r = rep2(s0.y); ffma2(c[0][0], r, v1a); ffma2(c[0][1], r, v1b);
            r = rep2(s1.x); ffma2(c[1][0], r, v0a); ffma2(c[1][1], r, v0b);
            r = rep2(s1.y); ffma2(c[1][0], r, v1a); ffma2(c[1][1], r, v1b);
            r = rep2(s2.x); ffma2(c[2][0], r, v0a); ffma2(c[2][1], r, v0b);
            r = rep2(s2.y); ffma2(c[2][0], r, v1a); ffma2(c[2][1], r, v1b);
            r = rep2(s3.x); ffma2(c[3][0], r, v0a); ffma2(c[3][1], r, v0b);
            r = rep2(s3.y); ffma2(c[3][0], r, v1a); ffma2(c[3][1], r, v1b);
        }
    }
    // reduce the two kk-halves through cbuf
    __syncthreads();
    if (half == 0) {
        #pragma unroll
        for (int i = 0; i < 4; i++) {
            float2 lo = upk(c[i][0]), hi = upk(c[i][1]);
            *(float4*)(cbuf + (q0+i)*VP + pd) = make_float4(lo.x, lo.y, hi.x, hi.y);
        }
    }
    __syncthreads();
    if (half == 1) {
        #pragma unroll
        for (int i = 0; i < 4; i++) {
            float2 lo = upk(c[i][0]), hi = upk(c[i][1]);
            float4 o = *(float4*)(cbuf + (q0+i)*VP + pd);
            o.x += lo.x; o.y += lo.y; o.z += hi.x; o.w += hi.y;
            *(float4*)(cbuf + (q0+i)*VP + pd) = o;
        }
    }
    __syncthreads();
    {
        const int row = t >> 3, c8 = (t & 7)*8;
        const float iv = sinv[row];
        float4 a = *(float4*)(cbuf + row*VP + c8);
        float4 b4 = *(float4*)(cbuf + row*VP + c8 + 4);
        a.x *= iv; a.y *= iv; a.z *= iv; a.w *= iv;
        b4.x *= iv; b4.y *= iv; b4.z *= iv; b4.w *= iv;
        float* dp = g_ctx + ((size_t)b*LL + qbase + row)*HID + h*DH + c8;
        *(float4*)(dp)     = a;
        *(float4*)(dp + 4) = b4;
    }
}

// =====================================================================
// Kernel 3: out = LN(ctx @ Wo + bo + residual). 256 thr, 8 tokens/block
// =====================================================================
__global__ void outproj_kernel(const float* __restrict__ Qin, const float* __restrict__ Wo,
                               const float* __restrict__ bo, const float* __restrict__ lng,
                               const float* __restrict__ lnb, float* __restrict__ out) {
    extern __shared__ float osm[];
    float* sWo = osm;                 // 512*19
    float* scx = sWo + HID*DM;        // 8*512
    float* sx  = scx + 8*HID;         // 8*20
    const int t = threadIdx.x, warp = t >> 5, lane = t & 31;
    for (int i = t; i < HID*DM; i += 256) sWo[i] = Wo[i];
    const int n = blockIdx.x*8 + warp;
    #pragma unroll
    for (int k = 0; k < 4; k++)
        *(float4*)(scx + warp*HID + lane*4 + 128*k) =
            *(const float4*)(g_ctx + (size_t)n*HID + lane*4 + 128*k);
    __syncthreads();

    float x = 0.f;
    if (lane < DM) {
        float a0 = 0.f, a1 = 0.f, a2 = 0.f, a3 = 0.f;
        const float* cs = scx + warp*HID;
        for (int i = 0; i < HID; i += 4) {
            a0 += cs[i+0]*sWo[(i+0)*DM + lane];
            a1 += cs[i+1]*sWo[(i+1)*DM + lane];
            a2 += cs[i+2]*sWo[(i+2)*DM + lane];
            a3 += cs[i+3]*sWo[(i+3)*DM + lane];
        }
        x = (a0+a1) + (a2+a3) + bo[lane] + Qin[(size_t)n*DM + lane];
        sx[warp*20 + lane] = x;
    }
    __syncwarp();
    if (lane < DM) {
        float mu = 0.f;
        #pragma unroll
        for (int j = 0; j < DM; j++) mu += sx[warp*20 + j];
        mu *= (1.0f/19.0f);
        float var = 0.f;
        #pragma unroll
        for (int j = 0; j < DM; j++) { float d = sx[warp*20 + j] - mu; var += d*d; }
        var *= (1.0f/19.0f);
        out[(size_t)n*DM + lane] = (x - mu)*rsqrtf(var + 1e-5f)*lng[lane] + lnb[lane];
    }
}

// =====================================================================
// Kernel 4: residual = Q
// =====================================================================
__global__ void copy_res_kernel(const float* __restrict__ Qin, float* __restrict__ dst) {
    const size_t i = ((size_t)blockIdx.x*256 + threadIdx.x)*4;
    *(float4*)(dst + i) = *(const float4*)(Qin + i);
}

// =====================================================================
extern "C" void kernel_launch(void* const* d_in, const int* in_sizes, int n_in,
                              void* d_out, int out_size) {
    const float* Q   = (const float*)d_in[0];
    const float* K   = (const float*)d_in[1];
    const float* V   = (const float*)d_in[2];
    const int*  mask = (const int*)d_in[3];
    const float* Wq  = (const float*)d_in[4];
    const float* bq  = (const float*)d_in[5];
    const float* Wk  = (const float*)d_in[6];
    const float* bk  = (const float*)d_in[7];
    const float* Wv  = (const float*)d_in[8];
    const float* bv  = (const float*)d_in[9];
    const float* Wo  = (const float*)d_in[10];
    const float* bo  = (const float*)d_in[11];
    const float* lng = (const float*)d_in[12];
    const float* lnb = (const float*)d_in[13];

    float* out  = (float*)d_out;
    float* attn = out + OUT_ELEMS;
    float* res  = attn + ATTN_ELEMS;

    const int ATT_SMEM = (MQ*LL + KTILE*VP + DH*32 + 32*VP) * (int)sizeof(float); // 182784
    cudaFuncSetAttribute(attn_kernel, cudaFuncAttributeMaxDynamicSharedMemorySize, ATT_SMEM);
    const int OUT_SMEM = (HID*DM + 8*HID + 8*20) * (int)sizeof(float);            // 55936
    cudaFuncSetAttribute(outproj_kernel, cudaFuncAttributeMaxDynamicSharedMemorySize, OUT_SMEM);

    proj_kernel<<<dim3(NTOK/32, 3), 256>>>(Q, K, V, Wq, Wk, Wv, bq, bk, bv);
    transpose_k_kernel<<<dim3(LL/128, BB*NH), 256>>>();
    attn_kernel<<<dim3(LL/MQ, BB*NH), 256, ATT_SMEM>>>(mask, attn);
    outproj_kernel<<<NTOK/8, 256, OUT_SMEM>>>(Q, Wo, bo, lng, lnb, out);
    copy_res_kernel<<<OUT_ELEMS/4/256, 256>>>(Q, res);
}

// round 12
// speedup vs baseline: 1.8727x; 1.7008x over previous
#include <cuda_runtime.h>
#include <cuda_bf16.h>
#include <cstdint>
#include <cstddef>

#define DM 19
#define HID 512
#define NH 8
#define DH 64
#define BB 16
#define LL 1024
#define NTOK (BB*LL)
#define QT 128

#define OUT_ELEMS   (NTOK*DM)
#define ATTN_ELEMS  ((size_t)BB*NH*LL*LL)

// ---- scratch ----
__device__ __align__(256) __nv_bfloat16 g_qs[(size_t)BB*NH*LL*128];  // [bh][l][hi64|lo64]
__device__ __align__(256) __nv_bfloat16 g_ks[(size_t)BB*NH*LL*128];
__device__ __align__(256) float         g_v [(size_t)BB*NH*LL*DH];
__device__ __align__(256) __nv_bfloat16 g_vT[(size_t)BB*NH*DH*LL];   // [bh][d][l]
__device__ __align__(256) float         g_ctx[(size_t)NTOK*HID];
__device__ __align__(256) float         g_inv[(size_t)BB*NH*LL];     // 1/rowsum

// ---- helpers ----
__device__ __forceinline__ uint32_t s2u(const void* p) {
    uint32_t a;
    asm("{ .reg .u64 t; cvta.to.shared.u64 t, %1; cvt.u32.u64 %0, t; }" : "=r"(a) : "l"(p));
    return a;
}
__device__ __forceinline__ void cp16(uint32_t dst, const void* src) {
    asm volatile("cp.async.cg.shared.global [%0], [%1], 16;"
                 :: "r"(dst), "l"(__cvta_generic_to_global(src)));
}
#define CP_COMMIT() asm volatile("cp.async.commit_group;" ::: "memory")
#define CP_WAIT(n)  asm volatile("cp.async.wait_group %0;" :: "n"(n) : "memory")

#define MMA16816(c, a0, a1, a2, a3, b0, b1)                                   \
    asm volatile("mma.sync.aligned.m16n8k16.row.col.f32.bf16.bf16.f32 "       \
        "{%0,%1,%2,%3}, {%4,%5,%6,%7}, {%8,%9}, {%0,%1,%2,%3};"               \
        : "+f"((c)[0]), "+f"((c)[1]), "+f"((c)[2]), "+f"((c)[3])              \
        : "r"(a0), "r"(a1), "r"(a2), "r"(a3), "r"(b0), "r"(b1))

__device__ __forceinline__ uint32_t pbf2(float a, float b) {
    __nv_bfloat162 t = __floats2bfloat162_rn(a, b);
    return *reinterpret_cast<uint32_t*>(&t);
}

// =====================================================================
// Kernel 1: QKV projections. Q,K -> split bf16 [hi|lo]; V -> fp32
// =====================================================================
__global__ void proj_kernel(const float* __restrict__ Xq, const float* __restrict__ Xk,
                            const float* __restrict__ Xv,
                            const float* __restrict__ Wq, const float* __restrict__ Wk,
                            const float* __restrict__ Wv,
                            const float* __restrict__ bq, const float* __restrict__ bk,
                            const float* __restrict__ bv) {
    __shared__ float sW[DM*HID];
    __shared__ float sX[32*20];
    const int which = blockIdx.y;
    const float* X    = (which == 0) ? Xq : (which == 1) ? Xk : Xv;
    const float* W    = (which == 0) ? Wq : (which == 1) ? Wk : Wv;
    const float* bias = (which == 0) ? bq : (which == 1) ? bk : bv;

    const int t = threadIdx.x;
    for (int i = t; i < DM*HID; i += 256) sW[i] = W[i];
    const int base = blockIdx.x * 32;
    for (int i = t; i < 32*DM; i += 256) {
        int r = i / DM, m = i - r*DM;
        sX[r*20 + m] = X[(size_t)(base + r)*DM + m];
    }
    __syncthreads();

    const int bidx = base >> 10;
    const int lbase = base & 1023;
    #pragma unroll
    for (int cc = 0; cc < 2; cc++) {
        const int c = t + cc*256;
        const int h = c >> 6, d = c & 63;
        const float bval = bias[c];
        if (which < 2) {
            __nv_bfloat16* dp = (which == 0 ? g_qs : g_ks)
                + ((size_t)(bidx*NH + h)*LL + lbase)*128 + d;
            for (int r = 0; r < 32; r++) {
                float acc = bval;
                #pragma unroll
                for (int m = 0; m < DM; m++) acc += sX[r*20 + m] * sW[m*HID + c];
                __nv_bfloat16 hi = __float2bfloat16(acc);
                __nv_bfloat16 lo = __float2bfloat16(acc - __bfloat162float(hi));
                dp[(size_t)r*128]      = hi;
                dp[(size_t)r*128 + 64] = lo;
            }
        } else {
            float* dp = g_v + ((size_t)(bidx*NH + h)*LL + lbase)*DH + d;
            for (int r = 0; r < 32; r++) {
                float acc = bval;
                #pragma unroll
                for (int m = 0; m < DM; m++) acc += sX[r*20 + m] * sW[m*HID + c];
                dp[(size_t)r*DH] = acc;
            }
        }
    }
}

// =====================================================================
// Kernel 1b: V transpose  g_v[bh][l][d] fp32 -> g_vT[bh][d][l] bf16
// =====================================================================
__global__ void transpose_v_kernel() {
    __shared__ float ts[128*65];
    const int t = threadIdx.x;
    const int bh = blockIdx.y;
    const int lbase = blockIdx.x * 128;
    const float* src = g_v + ((size_t)bh*LL + lbase)*DH;
    #pragma unroll
    for (int j = 0; j < 8; j++) {
        int idx = t + j*256;
        int r = idx >> 4, d4 = (idx & 15)*4;
        float4 a = *(const float4*)(src + (size_t)r*DH + d4);
        ts[r*65 + d4 + 0] = a.x; ts[r*65 + d4 + 1] = a.y;
        ts[r*65 + d4 + 2] = a.z; ts[r*65 + d4 + 3] = a.w;
    }
    __syncthreads();
    #pragma unroll
    for (int j = 0; j < 4; j++) {
        int idx = t + j*256;
        int d = idx >> 4, c8 = (idx & 15)*8;
        uint4 o;
        o.x = pbf2(ts[(c8+0)*65 + d], ts[(c8+1)*65 + d]);
        o.y = pbf2(ts[(c8+2)*65 + d], ts[(c8+3)*65 + d]);
        o.z = pbf2(ts[(c8+4)*65 + d], ts[(c8+5)*65 + d]);
        o.w = pbf2(ts[(c8+6)*65 + d], ts[(c8+7)*65 + d]);
        *(uint4*)(g_vT + ((size_t)bh*DH + d)*LL + lbase + c8) = o;
    }
}

// =====================================================================
// Kernel 2: mma.sync attention. grid (8, 128), 256 threads, smem 208896
// Per CTA: 128 q x 1024 k, 64-key chunks, cp.async double buffer.
// Writes UNNORMALIZED e to attn (fp32) + 1/rowsum to g_inv; ctx to g_ctx.
// =====================================================================
#define SQ_  0u
#define SK0_ 51200u
#define SK1_ 76800u
#define SV0_ 102400u
#define SV1_ 111616u
#define SM0_ 120832u
#define SM1_ 155648u
#define SP_  190464u
#define ATT_SMEM 208896

__device__ __forceinline__ void load_kvm(uint32_t sb, int buf, int cb, int bh, int b,
                                         int qbase, const int* __restrict__ mask, int t) {
    const uint32_t sk = sb + (buf ? SK1_ : SK0_);
    const uint32_t sv = sb + (buf ? SV1_ : SV0_);
    const uint32_t sm = sb + (buf ? SM1_ : SM0_);
    const __nv_bfloat16* ks = g_ks + ((size_t)bh*LL + cb)*128;
    #pragma unroll
    for (int j = 0; j < 6; j++) {                        // K: [hi|hi|lo], 64 keys x 24 f4
        int idx = t + j*256; int key = idx/24, p = idx%24; int sf = (p < 8) ? p : p - 8;
        cp16(sk + key*400 + p*16, ks + (size_t)key*128 + sf*8);
    }
    const __nv_bfloat16* vt = g_vT + (size_t)bh*DH*LL + cb;
    #pragma unroll
    for (int j = 0; j < 2; j++) {                        // V: 64 d x 8 f4
        int idx = t + j*256; int d = idx >> 3, p = idx & 7;
        cp16(sv + d*144 + p*16, vt + (size_t)d*LL + p*8);
    }
    const int* mp = mask + ((size_t)b*LL + qbase)*LL + cb;
    #pragma unroll
    for (int j = 0; j < 8; j++) {                        // mask: 128 q x 16 f4
        int idx = t + j*256; int row = idx >> 4, p = idx & 15;
        cp16(sm + row*272 + p*16, mp + (size_t)row*LL + p*4);
    }
}

__global__ __launch_bounds__(256, 1)
void attn_kernel(const int* __restrict__ mask, float* __restrict__ attn_out) {
    extern __shared__ char smem[];
    const uint32_t sb = s2u(smem);
    const int t = threadIdx.x;
    const int wid = t >> 5, lane = t & 31;
    const int g = lane >> 2, m = lane & 3;
    const int bh = blockIdx.y, b = bh >> 3, h = bh & 7;
    const int qbase = blockIdx.x * QT;
    const int r1 = wid*16 + g, r2 = r1 + 8;
    const float INVSCALE = 0.13258252147247766f;   // sqrt(9/512)

    // prologue: Q tile + chunk0 (group 0), chunk1 (group 1)
    {
        const __nv_bfloat16* qs = g_qs + ((size_t)bh*LL + qbase)*128;
        #pragma unroll
        for (int j = 0; j < 12; j++) {                   // Q: [hi|lo|hi], 128 q x 24 f4
            int idx = t + j*256; int row = idx/24, p = idx%24; int sf = (p < 16) ? p : p - 16;
            cp16(sb + SQ_ + row*400 + p*16, qs + (size_t)row*128 + sf*8);
        }
        load_kvm(sb, 0, 0, bh, b, qbase, mask, t);
        CP_COMMIT();
        load_kvm(sb, 1, 64, bh, b, qbase, mask, t);
        CP_COMMIT();
    }

    const uint32_t* Qp = (const uint32_t*)(smem + SQ_);
    uint32_t* Pp = (uint32_t*)(smem + SP_);
    float cacc[8][4] = {};
    float sumA = 0.f, sumB = 0.f;
    const size_t bhrow = (size_t)bh*LL + qbase;

    for (int tt = 0; tt < 16; tt++) {
        if (tt == 15) { CP_WAIT(0); } else { CP_WAIT(1); }
        __syncthreads();
        const int buf = tt & 1;
        const uint32_t* Kp = (const uint32_t*)(smem + (buf ? SK1_ : SK0_));
        const uint32_t* Vp = (const uint32_t*)(smem + (buf ? SV1_ : SV0_));
        const int*      Mp = (const int*)     (smem + (buf ? SM1_ : SM0_));
        const int cb = tt*64;

        // ---- scores: 8 n-tiles x 12 k-steps (K-dim 192 = split bf16) ----
        float acc[8][4] = {};
        #pragma unroll
        for (int ks = 0; ks < 12; ks++) {
            uint32_t a0 = Qp[r1*100 + ks*8 + m];
            uint32_t a1 = Qp[r2*100 + ks*8 + m];
            uint32_t a2 = Qp[r1*100 + ks*8 + m + 4];
            uint32_t a3 = Qp[r2*100 + ks*8 + m + 4];
            #pragma unroll
            for (int nt = 0; nt < 8; nt++) {
                const int key = nt*8 + g;
                uint32_t b0 = Kp[key*100 + ks*8 + m];
                uint32_t b1 = Kp[key*100 + ks*8 + m + 4];
                MMA16816(acc[nt], a0, a1, a2, a3, b0, b1);
            }
        }
        // ---- mask + exp + sums + attn(e) store + P(bf16) ----
        #pragma unroll
        for (int nt = 0; nt < 8; nt++) {
            int2 mA = *(const int2*)(Mp + r1*68 + nt*8 + 2*m);
            int2 mB = *(const int2*)(Mp + r2*68 + nt*8 + 2*m);
            float e00 = mA.x ? 0.f : __expf(acc[nt][0]*INVSCALE);
            float e01 = mA.y ? 0.f : __expf(acc[nt][1]*INVSCALE);
            float e10 = mB.x ? 0.f : __expf(acc[nt][2]*INVSCALE);
            float e11 = mB.y ? 0.f : __expf(acc[nt][3]*INVSCALE);
            sumA += e00 + e01; sumB += e10 + e11;
            *(float2*)(attn_out + (bhrow + r1)*LL + cb + nt*8 + 2*m) = make_float2(e00, e01);
            *(float2*)(attn_out + (bhrow + r2)*LL + cb + nt*8 + 2*m) = make_float2(e10, e11);
            Pp[r1*36 + nt*4 + m] = pbf2(e00, e01);
            Pp[r2*36 + nt*4 + m] = pbf2(e10, e11);
        }
        __syncwarp();
        // ---- PV: ctx += P @ V  (8 d-tiles x 4 k-steps) ----
        #pragma unroll
        for (int ks = 0; ks < 4; ks++) {
            uint32_t a0 = Pp[r1*36 + ks*8 + m];
            uint32_t a1 = Pp[r2*36 + ks*8 + m];
            uint32_t a2 = Pp[r1*36 + ks*8 + m + 4];
            uint32_t a3 = Pp[r2*36 + ks*8 + m + 4];
            #pragma unroll
            for (int nt = 0; nt < 8; nt++) {
                const int dd = nt*8 + g;
                uint32_t b0 = Vp[dd*36 + ks*8 + m];
                uint32_t b1 = Vp[dd*36 + ks*8 + m + 4];
                MMA16816(cacc[nt], a0, a1, a2, a3, b0, b1);
            }
        }
        __syncthreads();
        if (tt + 2 < 16) { load_kvm(sb, buf, (tt+2)*64, bh, b, qbase, mask, t); CP_COMMIT(); }
    }

    // ---- row sums -> inv ----
    sumA += __shfl_xor_sync(~0u, sumA, 1); sumA += __shfl_xor_sync(~0u, sumA, 2);
    sumB += __shfl_xor_sync(~0u, sumB, 1); sumB += __shfl_xor_sync(~0u, sumB, 2);
    const float invA = 1.0f / sumA, invB = 1.0f / sumB;
    if (m == 0) {
        g_inv[bhrow + r1] = invA;
        g_inv[bhrow + r2] = invB;
    }
    // ---- ctx out ----
    float* c1p = g_ctx + ((size_t)b*LL + qbase + r1)*HID + h*DH;
    float* c2p = g_ctx + ((size_t)b*LL + qbase + r2)*HID + h*DH;
    #pragma unroll
    for (int nt = 0; nt < 8; nt++) {
        *(float2*)(c1p + nt*8 + 2*m) = make_float2(cacc[nt][0]*invA, cacc[nt][1]*invA);
        *(float2*)(c2p + nt*8 + 2*m) = make_float2(cacc[nt][2]*invB, cacc[nt][3]*invB);
    }
}

// =====================================================================
// Kernel 2b: attn *= 1/rowsum  (in-place stream)
// =====================================================================
__global__ void attn_scale_kernel(float* __restrict__ attn) {
    const size_t i = ((size_t)blockIdx.x*256 + threadIdx.x);
    const size_t base = i*4;
    const float inv = g_inv[base >> 10];
    float4 v = *(float4*)(attn + base);
    v.x *= inv; v.y *= inv; v.z *= inv; v.w *= inv;
    *(float4*)(attn + base) = v;
}

// =====================================================================
// Kernel 3: out = LN(ctx @ Wo + bo + residual). 256 thr, 8 tokens/block
// =====================================================================
__global__ void outproj_kernel(const float* __restrict__ Qin, const float* __restrict__ Wo,
                               const float* __restrict__ bo, const float* __restrict__ lng,
                               const float* __restrict__ lnb, float* __restrict__ out) {
    extern __shared__ float osm[];
    float* sWo = osm;
    float* scx = sWo + HID*DM;
    float* sx  = scx + 8*HID;
    const int t = threadIdx.x, warp = t >> 5, lane = t & 31;
    for (int i = t; i < HID*DM; i += 256) sWo[i] = Wo[i];
    const int n = blockIdx.x*8 + warp;
    #pragma unroll
    for (int k = 0; k < 4; k++)
        *(float4*)(scx + warp*HID + lane*4 + 128*k) =
            *(const float4*)(g_ctx + (size_t)n*HID + lane*4 + 128*k);
    __syncthreads();

    float x = 0.f;
    if (lane < DM) {
        float a0 = 0.f, a1 = 0.f, a2 = 0.f, a3 = 0.f;
        const float* cs = scx + warp*HID;
        for (int i = 0; i < HID; i += 4) {
            a0 += cs[i+0]*sWo[(i+0)*DM + lane];
            a1 += cs[i+1]*sWo[(i+1)*DM + lane];
            a2 += cs[i+2]*sWo[(i+2)*DM + lane];
            a3 += cs[i+3]*sWo[(i+3)*DM + lane];
        }
        x = (a0+a1) + (a2+a3) + bo[lane] + Qin[(size_t)n*DM + lane];
        sx[warp*20 + lane] = x;
    }
    __syncwarp();
    if (lane < DM) {
        float mu = 0.f;
        #pragma unroll
        for (int j = 0; j < DM; j++) mu += sx[warp*20 + j];
        mu *= (1.0f/19.0f);
        float var = 0.f;
        #pragma unroll
        for (int j = 0; j < DM; j++) { float d = sx[warp*20 + j] - mu; var += d*d; }
        var *= (1.0f/19.0f);
        out[(size_t)n*DM + lane] = (x - mu)*rsqrtf(var + 1e-5f)*lng[lane] + lnb[lane];
    }
}

// =====================================================================
// Kernel 4: residual = Q
// =====================================================================
__global__ void copy_res_kernel(const float* __restrict__ Qin, float* __restrict__ dst) {
    const size_t i = ((size_t)blockIdx.x*256 + threadIdx.x)*4;
    *(float4*)(dst + i) = *(const float4*)(Qin + i);
}

// =====================================================================
extern "C" void kernel_launch(void* const* d_in, const int* in_sizes, int n_in,
                              void* d_out, int out_size) {
    const float* Q   = (const float*)d_in[0];
    const float* K   = (const float*)d_in[1];
    const float* V   = (const float*)d_in[2];
    const int*  mask = (const int*)d_in[3];
    const float* Wq  = (const float*)d_in[4];
    const float* bq  = (const float*)d_in[5];
    const float* Wk  = (const float*)d_in[6];
    const float* bk  = (const float*)d_in[7];
    const float* Wv  = (const float*)d_in[8];
    const float* bv  = (const float*)d_in[9];
    const float* Wo  = (const float*)d_in[10];
    const float* bo  = (const float*)d_in[11];
    const float* lng = (const float*)d_in[12];
    const float* lnb = (const float*)d_in[13];

    float* out  = (float*)d_out;
    float* attn = out + OUT_ELEMS;
    float* res  = attn + ATTN_ELEMS;

    cudaFuncSetAttribute(attn_kernel, cudaFuncAttributeMaxDynamicSharedMemorySize, ATT_SMEM);
    const int OUT_SMEM = (HID*DM + 8*HID + 8*20) * (int)sizeof(float);
    cudaFuncSetAttribute(outproj_kernel, cudaFuncAttributeMaxDynamicSharedMemorySize, OUT_SMEM);

    proj_kernel<<<dim3(NTOK/32, 3), 256>>>(Q, K, V, Wq, Wk, Wv, bq, bk, bv);
    transpose_v_kernel<<<dim3(LL/128, BB*NH), 256>>>();
    attn_kernel<<<dim3(LL/QT, BB*NH), 256, ATT_SMEM>>>(mask, attn);
    attn_scale_kernel<<<(int)(ATTN_ELEMS/4/256), 256>>>(attn);
    outproj_kernel<<<NTOK/8, 256, OUT_SMEM>>>(Q, Wo, bo, lng, lnb, out);
    copy_res_kernel<<<OUT_ELEMS/4/256, 256>>>(Q, res);
}